// round 5
// baseline (speedup 1.0000x reference)
#include <cuda_runtime.h>

// Conv4d via f32x2 FFMA2 with duplicated-x smem (no register packing).
// x(2,8,16,40,40,40) * W(3,32,8,3,3,3) + bias(3,32) -> out(2,32,16,40,40,40)
// Block: 160 thr, tile 4d x 8h x 40w at fixed (b,t,co-group-of-8).
// Thread: 4 co-pairs x 8 w = 32 u64 accs. Phase = (kt, ci): stage 1 ci slab dup'd.

typedef unsigned long long u64;

__device__ __forceinline__ u64 pack2(float lo, float hi) {
    u64 r; asm("mov.b64 %0, {%1, %2};" : "=l"(r) : "f"(lo), "f"(hi)); return r;
}
__device__ __forceinline__ void unpack2(float& lo, float& hi, u64 v) {
    asm("mov.b64 {%0, %1}, %2;" : "=f"(lo), "=f"(hi) : "l"(v));
}
__device__ __forceinline__ u64 ffma2(u64 a, u64 b, u64 c) {
    u64 d; asm("fma.rn.f32x2 %0, %1, %2, %3;" : "=l"(d) : "l"(a), "l"(b), "l"(c)); return d;
}

#define NT 160

__global__ void __launch_bounds__(NT, 4) conv4d_kernel(
    const float* __restrict__ x, const float* __restrict__ weight,
    const float* __restrict__ bias, float* __restrict__ out)
{
    // dup'd x slab: [dd6][hh10][pair46], each pair = (v,v). 2760 u64 = 22.1 KB
    __shared__ __align__(16) u64 sxd[6 * 10 * 46];
    // weights: [kt][ci8][kd][kh][kw][co8] floats = [..][cp4] u64 pairs. 20.7 KB
    __shared__ __align__(16) float sw[3 * 8 * 27 * 8];

    const int tid = threadIdx.x;
    const int hl  = tid & 7;            // 0..7  (fast: conflict-free LDS.128 rows)
    const int dl  = (tid >> 3) & 3;     // 0..3
    const int wg  = tid >> 5;           // 0..4 -> w0 = wg*8
    const int w0  = wg * 8;

    const int bx  = blockIdx.x;         // 0..49 -> (d0,h0)
    const int cog = blockIdx.y;         // 0..3
    const int bz  = blockIdx.z;         // 0..31 -> (b,t)
    const int d0  = (bx % 10) * 4;
    const int h0  = (bx / 10) * 8;
    const int b   = bz >> 4;
    const int t   = bz & 15;

    // one-time zero (invalid halo cells are block-invariant across phases)
    for (int idx = tid; idx < 6 * 10 * 46; idx += NT) sxd[idx] = 0ull;

    // one-time weight stage: [kt][ci][kd][kh][kw][co8]
    for (int idx = tid; idx < 5184; idx += NT) {
        int co = idx & 7;
        int r  = idx >> 3;
        int kw = r % 3; r /= 3;
        int kh = r % 3; r /= 3;
        int kd = r % 3; r /= 3;
        int ci = r & 7;
        int kt = r >> 3;
        sw[idx] = weight[(kt * 32 + cog * 8 + co) * 216 + ci * 27 + kd * 9 + kh * 3 + kw];
    }

    // accumulators init with effective bias
    u64 acc[4][8];
    #pragma unroll
    for (int cp = 0; cp < 4; ++cp) {
        float s0 = 0.f, s1 = 0.f;
        #pragma unroll
        for (int kt = 0; kt < 3; ++kt) {
            int tf = t + kt - 1;
            if (tf >= 0 && tf < 16) {
                s0 += bias[kt * 32 + cog * 8 + cp * 2];
                s1 += bias[kt * 32 + cog * 8 + cp * 2 + 1];
            }
        }
        u64 sv = pack2(s0, s1);
        #pragma unroll
        for (int wi = 0; wi < 8; ++wi) acc[cp][wi] = sv;
    }

    const int sww = tid % 40;           // staging: w column owned by this thread
    const int sr0 = tid / 40;           // staging: starting row (0..3)

    for (int kt = 0; kt < 3; ++kt) {
        const int tf = t + kt - 1;
        if (tf < 0 || tf >= 16) continue;               // uniform across block
        const float* xg = x + b * 8192000 + tf * 64000;

        #pragma unroll 1
        for (int ci = 0; ci < 8; ++ci) {
            const float* xgc = xg + ci * 1024000;
            __syncthreads();
            // stage slab: 6 dd x 10 hh x 40 ww, write dup pairs
            #pragma unroll 1
            for (int r = 0; r < 15; ++r) {
                int row = sr0 + r * 4;                  // 0..59
                int dd = row / 10, hh = row - dd * 10;
                int gd = d0 + dd - 1, gh = h0 + hh - 1;
                if ((unsigned)gd < 40u && (unsigned)gh < 40u) {
                    float v = xgc[gd * 1600 + gh * 40 + sww];
                    sxd[row * 46 + sww + 1] = pack2(v, v);
                }
            }
            __syncthreads();

            const u64* wci = (const u64*)sw + (kt * 8 + ci) * 27 * 4;
            #pragma unroll 1
            for (int kd = 0; kd < 3; ++kd) {
                #pragma unroll
                for (int kh = 0; kh < 3; ++kh) {
                    const u64* xp = &sxd[((dl + kd) * 10 + hl + kh) * 46 + w0];
                    u64 xx[10];
                    #pragma unroll
                    for (int j = 0; j < 10; ++j) xx[j] = xp[j];   // 5x LDS.128
                    #pragma unroll
                    for (int kw = 0; kw < 3; ++kw) {
                        const u64* wp = wci + (kd * 9 + kh * 3 + kw) * 4;
                        u64 wv0 = wp[0], wv1 = wp[1], wv2 = wp[2], wv3 = wp[3];
                        #pragma unroll
                        for (int wi = 0; wi < 8; ++wi) {
                            acc[0][wi] = ffma2(xx[wi + kw], wv0, acc[0][wi]);
                            acc[1][wi] = ffma2(xx[wi + kw], wv1, acc[1][wi]);
                            acc[2][wi] = ffma2(xx[wi + kw], wv2, acc[2][wi]);
                            acc[3][wi] = ffma2(xx[wi + kw], wv3, acc[3][wi]);
                        }
                    }
                }
            }
        }
    }

    // epilogue
    const int obase = ((b * 32 + cog * 8) * 16 + t) * 64000
                    + (d0 + dl) * 1600 + (h0 + hl) * 40 + w0;
    #pragma unroll
    for (int cp = 0; cp < 4; ++cp) {
        float lo[8], hi[8];
        #pragma unroll
        for (int wi = 0; wi < 8; ++wi) unpack2(lo[wi], hi[wi], acc[cp][wi]);
        float* o0 = out + obase + (cp * 2) * 1024000;
        float* o1 = o0 + 1024000;
        *reinterpret_cast<float4*>(o0)     = make_float4(lo[0], lo[1], lo[2], lo[3]);
        *reinterpret_cast<float4*>(o0 + 4) = make_float4(lo[4], lo[5], lo[6], lo[7]);
        *reinterpret_cast<float4*>(o1)     = make_float4(hi[0], hi[1], hi[2], hi[3]);
        *reinterpret_cast<float4*>(o1 + 4) = make_float4(hi[4], hi[5], hi[6], hi[7]);
    }
}

extern "C" void kernel_launch(void* const* d_in, const int* in_sizes, int n_in,
                              void* d_out, int out_size) {
    const float* x = nullptr; const float* w = nullptr; const float* bias = nullptr;
    for (int i = 0; i < n_in; ++i) {
        if (in_sizes[i] == 16384000)    x    = (const float*)d_in[i];
        else if (in_sizes[i] == 20736)  w    = (const float*)d_in[i];
        else if (in_sizes[i] == 96)     bias = (const float*)d_in[i];
    }
    float* out = (float*)d_out;
    dim3 grid(50, 4, 32);
    conv4d_kernel<<<grid, NT>>>(x, w, bias, out);
}

// round 7
// speedup vs baseline: 2.0385x; 2.0385x over previous
#include <cuda_runtime.h>
#include <cstdint>

// Conv4d via tf32 mma.sync.m16n8k8 implicit GEMM (family-target safe, no tcgen05).
// out[b,co,t,d,h,w] = sum_{kt,ci,kd,kh,kw} x[b,ci,t+kt-1,d+kd-1,h+kh-1,w+kw-1]*W[..] + bias_eff
// Per CTA: fixed (b,t,d), 3 h-rows x 40 w, all 32 co. m = hl*42+wi (126 valid of 128).
// Warps 2x2 over (m-half 64, co-half 16). Per tap: K=8 (ci), 8 mma per warp.

__device__ __forceinline__ float to_tf32(float v) {
    float r; asm("cvt.rna.tf32.f32 %0, %1;" : "=f"(r) : "f"(v)); return r;
}
__device__ __forceinline__ void mma16n8k8(float* d,
    uint32_t a0, uint32_t a1, uint32_t a2, uint32_t a3, uint32_t b0, uint32_t b1) {
    asm volatile("mma.sync.aligned.m16n8k8.row.col.f32.tf32.tf32.f32 "
                 "{%0,%1,%2,%3}, {%4,%5,%6,%7}, {%8,%9}, {%0,%1,%2,%3};"
                 : "+f"(d[0]), "+f"(d[1]), "+f"(d[2]), "+f"(d[3])
                 : "r"(a0), "r"(a1), "r"(a2), "r"(a3), "r"(b0), "r"(b1));
}

#define NT 128
#define SLAB_W (3 * 5 * 44 * 12)          // [dd3][hh5][ww44][ci8+pad4] words
#define SB_F2  (27 * 4 * 32)              // [tap27][ntile4][lane32] float2 frags
#define DYN_BYTES (SLAB_W * 4 + SB_F2 * 8)

__global__ void __launch_bounds__(NT) conv4d_mma(
    const float* __restrict__ x, const float* __restrict__ weight,
    const float* __restrict__ bias, float* __restrict__ out)
{
    extern __shared__ __align__(16) unsigned char dsm[];
    float*  slab = (float*)dsm;                    // 31680 B
    float2* sB   = (float2*)(dsm + SLAB_W * 4);    // 27648 B
    __shared__ float sbias[32];

    const int tid  = threadIdx.x;
    const int wid  = tid >> 5, lane = tid & 31;
    const int g    = lane >> 2, c = lane & 3;      // groupID / thread-in-group
    const int mh   = wid >> 1;                     // m base = mh*64
    const int nh   = wid & 1;                      // co base = nh*16

    const int hi = blockIdx.x;                     // 0..13
    const int dy = blockIdx.y;                     // 0..39 (output d)
    const int bz = blockIdx.z;                     // 0..31
    const int h0 = (hi < 13) ? hi * 3 : 37;        // overlap tile writes same values
    const int b  = bz >> 4;
    const int t  = bz & 15;

    if (tid < 32) {
        float s = 0.f;
        #pragma unroll
        for (int kt = 0; kt < 3; ++kt) {
            int tf = t + kt - 1;
            if (tf >= 0 && tf < 16) s += bias[kt * 32 + tid];
        }
        sbias[tid] = s;
    }
    // zero slab once; invalid (halo) cells are block-invariant, valid cells
    // are rewritten every kt phase before use.
    for (int i = tid; i < SLAB_W; i += NT) slab[i] = 0.f;

    // per-thread A row base offsets (words into slab), for 4 m-tiles x 2 rows
    int rowBase[4][2];
    #pragma unroll
    for (int mt = 0; mt < 4; ++mt) {
        #pragma unroll
        for (int j = 0; j < 2; ++j) {
            int r  = mh * 64 + mt * 16 + g + j * 8;
            int rr = (r < 126) ? r : 125;          // clamp pad rows (stores masked)
            int hl = rr / 42, wi = rr - hl * 42;
            rowBase[mt][j] = (hl * 44 + wi) * 12 + c;
        }
    }

    float acc[4][2][4];
    #pragma unroll
    for (int mt = 0; mt < 4; ++mt)
        #pragma unroll
        for (int nt = 0; nt < 2; ++nt)
            #pragma unroll
            for (int k = 0; k < 4; ++k) acc[mt][nt][k] = 0.f;

    for (int kt = 0; kt < 3; ++kt) {
        const int tf = t + kt - 1;
        if (tf < 0 || tf >= 16) continue;          // uniform across block
        __syncthreads();                           // smem reads of prev phase done

        // ---- stage x slab [dd3][hh5][ww44][ci8], tf32-rounded ----
        const float* xg = x + b * 8192000 + tf * 64000;
        for (int idx = tid; idx < 3 * 5 * 44; idx += NT) {
            int ww = idx % 44;
            int r2 = idx / 44;
            int hh = r2 % 5, dd = r2 / 5;
            int gd = dy + dd - 1, gh = h0 + hh - 1, gw = ww - 1;
            if ((unsigned)gd < 40u && (unsigned)gh < 40u && (unsigned)gw < 40u) {
                const float* xp = xg + gd * 1600 + gh * 40 + gw;
                float* sp = slab + idx * 12;
                #pragma unroll
                for (int ci = 0; ci < 8; ++ci) sp[ci] = to_tf32(xp[ci * 1024000]);
            }
        }
        // ---- stage B fragments: [tap][ntile][lane] = (w[k=c], w[k=c+4]) ----
        for (int idx = tid; idx < SB_F2; idx += NT) {
            int tap = idx >> 7;
            int r2  = idx & 127;
            int nt  = r2 >> 5;
            int le  = r2 & 31;
            int co  = nt * 8 + (le >> 2);
            int k0  = le & 3;
            float b0 = to_tf32(weight[((kt * 32 + co) * 8 + k0) * 27 + tap]);
            float b1 = to_tf32(weight[((kt * 32 + co) * 8 + k0 + 4) * 27 + tap]);
            sB[idx] = make_float2(b0, b1);
        }
        __syncthreads();

        // ---- tap loop: 27 taps, K=8 each ----
        #pragma unroll 3
        for (int tap = 0; tap < 27; ++tap) {
            const int kd = tap / 9, kh = (tap % 9) / 3, kw = tap % 3;
            const int shift = ((kd * 5 + kh) * 44 + kw) * 12;

            uint32_t a[4][4];
            #pragma unroll
            for (int mt = 0; mt < 4; ++mt) {
                const float* p0 = slab + rowBase[mt][0] + shift;
                const float* p1 = slab + rowBase[mt][1] + shift;
                a[mt][0] = __float_as_uint(p0[0]);
                a[mt][1] = __float_as_uint(p1[0]);
                a[mt][2] = __float_as_uint(p0[4]);
                a[mt][3] = __float_as_uint(p1[4]);
            }
            #pragma unroll
            for (int nt = 0; nt < 2; ++nt) {
                float2 bf = sB[(tap * 4 + nh * 2 + nt) * 32 + lane];
                uint32_t b0 = __float_as_uint(bf.x), b1 = __float_as_uint(bf.y);
                #pragma unroll
                for (int mt = 0; mt < 4; ++mt)
                    mma16n8k8(acc[mt][nt], a[mt][0], a[mt][1], a[mt][2], a[mt][3], b0, b1);
            }
        }
    }

    // ---- epilogue: bias + masked scatter stores ----
    // c-frag: regs {0,1} row=g, regs {2,3} row=g+8; cols = 2c + {0,1}
    #pragma unroll
    for (int mt = 0; mt < 4; ++mt) {
        #pragma unroll
        for (int j = 0; j < 2; ++j) {
            int r  = mh * 64 + mt * 16 + g + j * 8;
            if (r >= 126) continue;
            int hl = r / 42, wi = r - hl * 42;
            if (wi >= 40) continue;
            int sp = dy * 1600 + (h0 + hl) * 40 + wi;
            #pragma unroll
            for (int nt = 0; nt < 2; ++nt) {
                int co0 = nh * 16 + nt * 8 + 2 * c;
                float v0 = acc[mt][nt][j * 2 + 0] + sbias[co0];
                float v1 = acc[mt][nt][j * 2 + 1] + sbias[co0 + 1];
                out[((b * 32 + co0) * 16 + t) * 64000 + sp]       = v0;
                out[((b * 32 + co0 + 1) * 16 + t) * 64000 + sp]   = v1;
            }
        }
    }
}

extern "C" void kernel_launch(void* const* d_in, const int* in_sizes, int n_in,
                              void* d_out, int out_size) {
    const float* x = nullptr; const float* w = nullptr; const float* bias = nullptr;
    for (int i = 0; i < n_in; ++i) {
        if (in_sizes[i] == 16384000)    x    = (const float*)d_in[i];
        else if (in_sizes[i] == 20736)  w    = (const float*)d_in[i];
        else if (in_sizes[i] == 96)     bias = (const float*)d_in[i];
    }
    float* out = (float*)d_out;
    cudaFuncSetAttribute(conv4d_mma, cudaFuncAttributeMaxDynamicSharedMemorySize, DYN_BYTES);
    dim3 grid(14, 40, 32);
    conv4d_mma<<<grid, NT, DYN_BYTES>>>(x, w, bias, out);
}

// round 8
// speedup vs baseline: 4.0769x; 2.0000x over previous
#include <cuda_runtime.h>
#include <cstdint>

// Conv4d via tf32 mma.sync.m16n8k8 implicit GEMM, round 8.
// Pre-kernel bakes tf32 B fragments to gmem; main kernel: slab [ci][dd][hh][w],
// warp = 32 m-rows x 32 co, immediate-offset LDS, 6 CTAs/SM.

__device__ __forceinline__ float to_tf32(float v) {
    float r; asm("cvt.rna.tf32.f32 %0, %1;" : "=f"(r) : "f"(v)); return r;
}
__device__ __forceinline__ void mma16n8k8(float* d,
    uint32_t a0, uint32_t a1, uint32_t a2, uint32_t a3, uint32_t b0, uint32_t b1) {
    asm volatile("mma.sync.aligned.m16n8k8.row.col.f32.tf32.tf32.f32 "
                 "{%0,%1,%2,%3}, {%4,%5,%6,%7}, {%8,%9}, {%0,%1,%2,%3};"
                 : "+f"(d[0]), "+f"(d[1]), "+f"(d[2]), "+f"(d[3])
                 : "r"(a0), "r"(a1), "r"(a2), "r"(a3), "r"(b0), "r"(b1));
}

// B fragments: [kt][tap][p(2)][lane(32)] float4 = (b0 b1 of nt=2p, b0 b1 of nt=2p+1)
__device__ float4 g_fB[3 * 27 * 2 * 32];

__global__ void prep_fB(const float* __restrict__ weight) {
    int i = blockIdx.x * blockDim.x + threadIdx.x;
    if (i >= 5184) return;
    int lane = i & 31;
    int p    = (i >> 5) & 1;
    int kttap = i >> 6;
    int tap = kttap % 27, kt = kttap / 27;
    int g = lane >> 2, k0 = lane & 3;
    int co0 = (2 * p) * 8 + g, co1 = co0 + 8;
    float4 f;
    f.x = to_tf32(weight[((kt * 32 + co0) * 8 + k0) * 27 + tap]);
    f.y = to_tf32(weight[((kt * 32 + co0) * 8 + k0 + 4) * 27 + tap]);
    f.z = to_tf32(weight[((kt * 32 + co1) * 8 + k0) * 27 + tap]);
    f.w = to_tf32(weight[((kt * 32 + co1) * 8 + k0 + 4) * 27 + tap]);
    g_fB[i] = f;
}

#define NT 128
#define PLANE 728                      // 3*5*48 = 720, +8 pad (mod 32 = 24: conflict-free c-planes)

__global__ void __launch_bounds__(NT, 6) conv4d_mma(
    const float* __restrict__ x, const float* __restrict__ bias,
    float* __restrict__ out)
{
    __shared__ __align__(16) float slab[8 * PLANE];   // [ci8][dd3][hh5][ww48] 23.3 KB
    __shared__ float sbias[32];

    const int tid  = threadIdx.x;
    const int wid  = tid >> 5, lane = tid & 31;
    const int g    = lane >> 2, c = lane & 3;

    const int hi = blockIdx.x;                 // 0..13
    const int dy = blockIdx.y;                 // output d
    const int bz = blockIdx.z;
    const int h0 = (hi < 13) ? hi * 3 : 37;    // overlap rows recompute same values
    const int b  = bz >> 4;
    const int t  = bz & 15;

    if (tid < 32) {
        float s = 0.f;
        #pragma unroll
        for (int kt = 0; kt < 3; ++kt) {
            int tf = t + kt - 1;
            if (tf >= 0 && tf < 16) s += bias[kt * 32 + tid];
        }
        sbias[tid] = s;
    }
    for (int i = tid; i < 8 * PLANE; i += NT) slab[i] = 0.f;   // halo/invalid rows stay 0

    // A row bases: rows r = wid*32 + mt*16 + g + j*8 (clamped; rows>=126 masked at store)
    const float* aPtr[2][2][2];                 // [cHalf][mt][j]
    #pragma unroll
    for (int mt = 0; mt < 2; ++mt)
        #pragma unroll
        for (int j = 0; j < 2; ++j) {
            int r  = wid * 32 + mt * 16 + g + j * 8;
            int rr = (r < 126) ? r : 125;
            int hl = rr / 42, wi = rr - hl * 42;
            int off = hl * 48 + wi + 3;         // +3: w column = gw+4, base kw=0 -> gw=wi-1
            aPtr[0][mt][j] = slab + c * PLANE + off;
            aPtr[1][mt][j] = slab + (c + 4) * PLANE + off;
        }

    float acc[2][4][4];
    #pragma unroll
    for (int mt = 0; mt < 2; ++mt)
        #pragma unroll
        for (int nt = 0; nt < 4; ++nt)
            #pragma unroll
            for (int k = 0; k < 4; ++k) acc[mt][nt][k] = 0.f;

    for (int kt = 0; kt < 3; ++kt) {
        const int tf = t + kt - 1;
        if (tf < 0 || tf >= 16) continue;       // uniform across block
        __syncthreads();                        // prior-phase reads / zero-fill done

        // ---- stage slab: 8ci x 3dd x 5hh rows, 10 float4 per row ----
        const float* xg = x + b * 8192000 + tf * 64000;
        for (int idx = tid; idx < 1200; idx += NT) {
            int ci  = idx / 150;
            int rem = idx - ci * 150;
            int row = rem / 10, q = rem - row * 10;
            int dd  = row / 5,  hh = row - dd * 5;
            int gd = dy + dd - 1, gh = h0 + hh - 1;
            if ((unsigned)gd < 40u && (unsigned)gh < 40u) {
                float4 v = *(const float4*)(xg + ci * 1024000 + gd * 1600 + gh * 40 + q * 4);
                v.x = to_tf32(v.x); v.y = to_tf32(v.y);
                v.z = to_tf32(v.z); v.w = to_tf32(v.w);
                *(float4*)(slab + ci * PLANE + dd * 240 + hh * 48 + 4 + q * 4) = v;
            }
        }
        __syncthreads();

        // ---- 27 taps: 2 LDG.128 (B) + 8 LDS.32 (A, imm offsets) + 8 MMA per warp ----
        const float4* fb = g_fB + (kt * 27) * 64 + lane;
        #pragma unroll 1
        for (int kd = 0; kd < 3; ++kd) {
            const int kdOff = kd * 240;
            #pragma unroll
            for (int kh = 0; kh < 3; ++kh) {
                #pragma unroll
                for (int kw = 0; kw < 3; ++kw) {
                    const int tap = kd * 9 + kh * 3 + kw;
                    const int sh  = kdOff + kh * 48 + kw;
                    float4 f0 = __ldg(fb + tap * 64);
                    float4 f1 = __ldg(fb + tap * 64 + 32);
                    #pragma unroll
                    for (int mt = 0; mt < 2; ++mt) {
                        uint32_t a0 = __float_as_uint(aPtr[0][mt][0][sh]);
                        uint32_t a1 = __float_as_uint(aPtr[0][mt][1][sh]);
                        uint32_t a2 = __float_as_uint(aPtr[1][mt][0][sh]);
                        uint32_t a3 = __float_as_uint(aPtr[1][mt][1][sh]);
                        mma16n8k8(acc[mt][0], a0, a1, a2, a3,
                                  __float_as_uint(f0.x), __float_as_uint(f0.y));
                        mma16n8k8(acc[mt][1], a0, a1, a2, a3,
                                  __float_as_uint(f0.z), __float_as_uint(f0.w));
                        mma16n8k8(acc[mt][2], a0, a1, a2, a3,
                                  __float_as_uint(f1.x), __float_as_uint(f1.y));
                        mma16n8k8(acc[mt][3], a0, a1, a2, a3,
                                  __float_as_uint(f1.z), __float_as_uint(f1.w));
                    }
                }
            }
        }
    }

    // ---- epilogue: bias + masked stores ----
    #pragma unroll
    for (int mt = 0; mt < 2; ++mt) {
        #pragma unroll
        for (int j = 0; j < 2; ++j) {
            int r = wid * 32 + mt * 16 + g + j * 8;
            if (r >= 126) continue;
            int hl = r / 42, wi = r - hl * 42;
            if (wi >= 40) continue;
            int sp = dy * 1600 + (h0 + hl) * 40 + wi;
            #pragma unroll
            for (int nt = 0; nt < 4; ++nt) {
                int co = nt * 8 + 2 * c;
                out[((b * 32 + co) * 16 + t) * 64000 + sp]     = acc[mt][nt][j * 2]     + sbias[co];
                out[((b * 32 + co + 1) * 16 + t) * 64000 + sp] = acc[mt][nt][j * 2 + 1] + sbias[co + 1];
            }
        }
    }
}

extern "C" void kernel_launch(void* const* d_in, const int* in_sizes, int n_in,
                              void* d_out, int out_size) {
    const float* x = nullptr; const float* w = nullptr; const float* bias = nullptr;
    for (int i = 0; i < n_in; ++i) {
        if (in_sizes[i] == 16384000)    x    = (const float*)d_in[i];
        else if (in_sizes[i] == 20736)  w    = (const float*)d_in[i];
        else if (in_sizes[i] == 96)     bias = (const float*)d_in[i];
    }
    float* out = (float*)d_out;
    prep_fB<<<21, 256>>>(w);
    dim3 grid(14, 40, 32);
    conv4d_mma<<<grid, NT>>>(x, bias, out);
}

// round 9
// speedup vs baseline: 4.5780x; 1.1229x over previous
#include <cuda_runtime.h>
#include <cstdint>

// Conv4d via tf32 mma.sync.m16n8k8 implicit GEMM, round 9.
// Warp = 64 m-rows x 32 co (mt=4, nt=4); CTA covers 2 d-layers (slab dd=4).
// B fragments baked by pre-kernel; B LDG halved per output, staging -33%.

__device__ __forceinline__ float to_tf32(float v) {
    float r; asm("cvt.rna.tf32.f32 %0, %1;" : "=f"(r) : "f"(v)); return r;
}
__device__ __forceinline__ void mma16n8k8(float* d,
    uint32_t a0, uint32_t a1, uint32_t a2, uint32_t a3, uint32_t b0, uint32_t b1) {
    asm volatile("mma.sync.aligned.m16n8k8.row.col.f32.tf32.tf32.f32 "
                 "{%0,%1,%2,%3}, {%4,%5,%6,%7}, {%8,%9}, {%0,%1,%2,%3};"
                 : "+f"(d[0]), "+f"(d[1]), "+f"(d[2]), "+f"(d[3])
                 : "r"(a0), "r"(a1), "r"(a2), "r"(a3), "r"(b0), "r"(b1));
}

// B fragments: [kt][tap][p(2)][lane(32)] float4 = (b0,b1 of nt=2p | b0,b1 of nt=2p+1)
__device__ float4 g_fB[3 * 27 * 2 * 32];

__global__ void prep_fB(const float* __restrict__ weight) {
    int i = blockIdx.x * blockDim.x + threadIdx.x;
    if (i >= 5184) return;
    int lane = i & 31;
    int p    = (i >> 5) & 1;
    int kttap = i >> 6;
    int tap = kttap % 27, kt = kttap / 27;
    int g = lane >> 2, k0 = lane & 3;
    int co0 = (2 * p) * 8 + g, co1 = co0 + 8;
    float4 f;
    f.x = to_tf32(weight[((kt * 32 + co0) * 8 + k0) * 27 + tap]);
    f.y = to_tf32(weight[((kt * 32 + co0) * 8 + k0 + 4) * 27 + tap]);
    f.z = to_tf32(weight[((kt * 32 + co1) * 8 + k0) * 27 + tap]);
    f.w = to_tf32(weight[((kt * 32 + co1) * 8 + k0 + 4) * 27 + tap]);
    g_fB[i] = f;
}

#define NT 128
#define PLANE 968                 // 4*5*48=960 +8 pad: c-plane bank offsets {0,8,16,24}

__global__ void __launch_bounds__(NT, 4) conv4d_mma(
    const float* __restrict__ x, const float* __restrict__ bias,
    float* __restrict__ out)
{
    __shared__ __align__(16) float slab[8 * PLANE];   // [ci8][dd4][hh5][ww48] 31 KB
    __shared__ float sbias[32];

    const int tid  = threadIdx.x;
    const int wid  = tid >> 5, lane = tid & 31;
    const int g    = lane >> 2, c = lane & 3;
    const int dsel = wid >> 1;                 // warp's output d-layer (0/1)
    const int mhalf= wid & 1;                  // warp's m half (0/1)

    const int hi  = blockIdx.x;                // 0..13
    const int dy0 = blockIdx.y * 2;            // output d base (2 layers/CTA)
    const int bz  = blockIdx.z;
    const int h0  = (hi < 13) ? hi * 3 : 37;   // overlap rows recompute same values
    const int b   = bz >> 4;
    const int t   = bz & 15;

    if (tid < 32) {
        float s = 0.f;
        #pragma unroll
        for (int kt = 0; kt < 3; ++kt) {
            int tf = t + kt - 1;
            if (tf >= 0 && tf < 16) s += bias[kt * 32 + tid];
        }
        sbias[tid] = s;
    }
    for (int i = tid; i < 8 * PLANE; i += NT) slab[i] = 0.f;   // halo stays 0

    // A row offsets (within a [dd][hh][w] block): rows r = mhalf*64 + mt*16 + g + j*8
    int rowOff[4][2];
    #pragma unroll
    for (int mt = 0; mt < 4; ++mt)
        #pragma unroll
        for (int j = 0; j < 2; ++j) {
            int r  = mhalf * 64 + mt * 16 + g + j * 8;
            int rr = (r < 126) ? r : 125;
            int hl = rr / 42, wi = rr - hl * 42;
            rowOff[mt][j] = hl * 48 + wi + 3;
        }
    const float* pc0 = slab + c * PLANE + dsel * 240;       // k = c plane, d base
    const float* pc1 = pc0 + 4 * PLANE;                     // k = c+4 plane

    float acc[4][4][4];
    #pragma unroll
    for (int mt = 0; mt < 4; ++mt)
        #pragma unroll
        for (int nt = 0; nt < 4; ++nt)
            #pragma unroll
            for (int k = 0; k < 4; ++k) acc[mt][nt][k] = 0.f;

    for (int kt = 0; kt < 3; ++kt) {
        const int tf = t + kt - 1;
        if (tf < 0 || tf >= 16) continue;       // uniform across block
        __syncthreads();

        // ---- stage slab: 8ci x 4dd x 5hh rows, 10 float4 per row ----
        const float* xg = x + b * 8192000 + tf * 64000;
        for (int idx = tid; idx < 1600; idx += NT) {
            int ci  = idx / 200;
            int rem = idx - ci * 200;
            int row = rem / 10, q = rem - row * 10;
            int dd  = row / 5,  hh = row - dd * 5;
            int gd = dy0 + dd - 1, gh = h0 + hh - 1;
            if ((unsigned)gd < 40u && (unsigned)gh < 40u) {
                float4 v = *(const float4*)(xg + ci * 1024000 + gd * 1600 + gh * 40 + q * 4);
                v.x = to_tf32(v.x); v.y = to_tf32(v.y);
                v.z = to_tf32(v.z); v.w = to_tf32(v.w);
                *(float4*)(slab + ci * PLANE + dd * 240 + hh * 48 + 4 + q * 4) = v;
            }
        }
        __syncthreads();

        // ---- 27 taps: 2 LDG.128 (B) + 16 LDS.32 (A) + 16 MMA per warp ----
        const float4* fb = g_fB + (kt * 27) * 64 + lane;
        #pragma unroll 1
        for (int kd = 0; kd < 3; ++kd) {
            const int kdOff = kd * 240;
            const float4* fbk = fb + kd * 9 * 64;
            #pragma unroll
            for (int kh = 0; kh < 3; ++kh) {
                #pragma unroll
                for (int kw = 0; kw < 3; ++kw) {
                    const int sh = kdOff + kh * 48 + kw;
                    float4 f0 = __ldg(fbk + (kh * 3 + kw) * 64);
                    float4 f1 = __ldg(fbk + (kh * 3 + kw) * 64 + 32);
                    uint32_t bb[4] = { __float_as_uint(f0.x), __float_as_uint(f0.y),
                                       __float_as_uint(f0.z), __float_as_uint(f0.w) };
                    uint32_t bb2[4] = { __float_as_uint(f1.x), __float_as_uint(f1.y),
                                        __float_as_uint(f1.z), __float_as_uint(f1.w) };
                    #pragma unroll
                    for (int mt = 0; mt < 4; ++mt) {
                        uint32_t a0 = __float_as_uint(pc0[rowOff[mt][0] + sh]);
                        uint32_t a1 = __float_as_uint(pc0[rowOff[mt][1] + sh]);
                        uint32_t a2 = __float_as_uint(pc1[rowOff[mt][0] + sh]);
                        uint32_t a3 = __float_as_uint(pc1[rowOff[mt][1] + sh]);
                        mma16n8k8(acc[mt][0], a0, a1, a2, a3, bb[0],  bb[1]);
                        mma16n8k8(acc[mt][1], a0, a1, a2, a3, bb[2],  bb[3]);
                        mma16n8k8(acc[mt][2], a0, a1, a2, a3, bb2[0], bb2[1]);
                        mma16n8k8(acc[mt][3], a0, a1, a2, a3, bb2[2], bb2[3]);
                    }
                }
            }
        }
    }

    // ---- epilogue: bias + masked stores ----
    const int dyw = dy0 + dsel;
    #pragma unroll
    for (int mt = 0; mt < 4; ++mt) {
        #pragma unroll
        for (int j = 0; j < 2; ++j) {
            int r = mhalf * 64 + mt * 16 + g + j * 8;
            if (r >= 126) continue;
            int hl = r / 42, wi = r - hl * 42;
            if (wi >= 40) continue;
            int sp = dyw * 1600 + (h0 + hl) * 40 + wi;
            #pragma unroll
            for (int nt = 0; nt < 4; ++nt) {
                int co = nt * 8 + 2 * c;
                out[((b * 32 + co) * 16 + t) * 64000 + sp]     = acc[mt][nt][j * 2]     + sbias[co];
                out[((b * 32 + co + 1) * 16 + t) * 64000 + sp] = acc[mt][nt][j * 2 + 1] + sbias[co + 1];
            }
        }
    }
}

extern "C" void kernel_launch(void* const* d_in, const int* in_sizes, int n_in,
                              void* d_out, int out_size) {
    const float* x = nullptr; const float* w = nullptr; const float* bias = nullptr;
    for (int i = 0; i < n_in; ++i) {
        if (in_sizes[i] == 16384000)    x    = (const float*)d_in[i];
        else if (in_sizes[i] == 20736)  w    = (const float*)d_in[i];
        else if (in_sizes[i] == 96)     bias = (const float*)d_in[i];
    }
    float* out = (float*)d_out;
    prep_fB<<<21, 256>>>(w);
    dim3 grid(14, 20, 32);
    conv4d_mma<<<grid, NT>>>(x, bias, out);
}

// round 10
// speedup vs baseline: 4.8299x; 1.0550x over previous
#include <cuda_runtime.h>
#include <cstdint>

// Conv4d via tf32 mma.sync.m16n8k8 implicit GEMM, round 10.
// R9 tiling (warp = 64m x 32co, CTA = 2 d-layers) + fully-unrolled 27-tap loop
// (immediate LDS offsets) + B-fragment prefetch pipelined one tap ahead.

__device__ __forceinline__ float to_tf32(float v) {
    float r; asm("cvt.rna.tf32.f32 %0, %1;" : "=f"(r) : "f"(v)); return r;
}
__device__ __forceinline__ void mma16n8k8(float* d,
    uint32_t a0, uint32_t a1, uint32_t a2, uint32_t a3, uint32_t b0, uint32_t b1) {
    asm volatile("mma.sync.aligned.m16n8k8.row.col.f32.tf32.tf32.f32 "
                 "{%0,%1,%2,%3}, {%4,%5,%6,%7}, {%8,%9}, {%0,%1,%2,%3};"
                 : "+f"(d[0]), "+f"(d[1]), "+f"(d[2]), "+f"(d[3])
                 : "r"(a0), "r"(a1), "r"(a2), "r"(a3), "r"(b0), "r"(b1));
}

// B fragments: [kt][tap][p(2)][lane(32)] float4 = (b0,b1 of nt=2p | b0,b1 of nt=2p+1)
__device__ float4 g_fB[3 * 27 * 2 * 32];

__global__ void prep_fB(const float* __restrict__ weight) {
    int i = blockIdx.x * blockDim.x + threadIdx.x;
    if (i >= 5184) return;
    int lane = i & 31;
    int p    = (i >> 5) & 1;
    int kttap = i >> 6;
    int tap = kttap % 27, kt = kttap / 27;
    int g = lane >> 2, k0 = lane & 3;
    int co0 = (2 * p) * 8 + g, co1 = co0 + 8;
    float4 f;
    f.x = to_tf32(weight[((kt * 32 + co0) * 8 + k0) * 27 + tap]);
    f.y = to_tf32(weight[((kt * 32 + co0) * 8 + k0 + 4) * 27 + tap]);
    f.z = to_tf32(weight[((kt * 32 + co1) * 8 + k0) * 27 + tap]);
    f.w = to_tf32(weight[((kt * 32 + co1) * 8 + k0 + 4) * 27 + tap]);
    g_fB[i] = f;
}

#define NT 128
#define PLANE 968                 // 4*5*48=960 +8 pad: c-plane bank offsets {0,8,16,24}

__global__ void __launch_bounds__(NT, 4) conv4d_mma(
    const float* __restrict__ x, const float* __restrict__ bias,
    float* __restrict__ out)
{
    __shared__ __align__(16) float slab[8 * PLANE];   // [ci8][dd4][hh5][ww48] 31 KB
    __shared__ float sbias[32];

    const int tid  = threadIdx.x;
    const int wid  = tid >> 5, lane = tid & 31;
    const int g    = lane >> 2, c = lane & 3;
    const int dsel = wid >> 1;                 // warp's output d-layer (0/1)
    const int mhalf= wid & 1;                  // warp's m half (0/1)

    const int hi  = blockIdx.x;                // 0..13
    const int dy0 = blockIdx.y * 2;            // output d base (2 layers/CTA)
    const int bz  = blockIdx.z;
    const int h0  = (hi < 13) ? hi * 3 : 37;   // overlap rows recompute same values
    const int b   = bz >> 4;
    const int t   = bz & 15;

    if (tid < 32) {
        float s = 0.f;
        #pragma unroll
        for (int kt = 0; kt < 3; ++kt) {
            int tf = t + kt - 1;
            if (tf >= 0 && tf < 16) s += bias[kt * 32 + tid];
        }
        sbias[tid] = s;
    }
    for (int i = tid; i < 8 * PLANE; i += NT) slab[i] = 0.f;   // halo stays 0

    // A row base pointers: rows r = mhalf*64 + mt*16 + g + j*8
    const float* aBase[4][2];
    #pragma unroll
    for (int mt = 0; mt < 4; ++mt)
        #pragma unroll
        for (int j = 0; j < 2; ++j) {
            int r  = mhalf * 64 + mt * 16 + g + j * 8;
            int rr = (r < 126) ? r : 125;
            int hl = rr / 42, wi = rr - hl * 42;
            aBase[mt][j] = slab + c * PLANE + dsel * 240 + hl * 48 + wi + 3;
        }

    float acc[4][4][4];
    #pragma unroll
    for (int mt = 0; mt < 4; ++mt)
        #pragma unroll
        for (int nt = 0; nt < 4; ++nt)
            #pragma unroll
            for (int k = 0; k < 4; ++k) acc[mt][nt][k] = 0.f;

    for (int kt = 0; kt < 3; ++kt) {
        const int tf = t + kt - 1;
        if (tf < 0 || tf >= 16) continue;       // uniform across block
        __syncthreads();

        // ---- stage slab: 8ci x 4dd x 5hh rows, 10 float4 per row ----
        const float* xg = x + b * 8192000 + tf * 64000;
        for (int idx = tid; idx < 1600; idx += NT) {
            int ci  = idx / 200;
            int rem = idx - ci * 200;
            int row = rem / 10, q = rem - row * 10;
            int dd  = row / 5,  hh = row - dd * 5;
            int gd = dy0 + dd - 1, gh = h0 + hh - 1;
            if ((unsigned)gd < 40u && (unsigned)gh < 40u) {
                float4 v = *(const float4*)(xg + ci * 1024000 + gd * 1600 + gh * 40 + q * 4);
                v.x = to_tf32(v.x); v.y = to_tf32(v.y);
                v.z = to_tf32(v.z); v.w = to_tf32(v.w);
                *(float4*)(slab + ci * PLANE + dd * 240 + hh * 48 + 4 + q * 4) = v;
            }
        }
        __syncthreads();

        // ---- 27 taps fully unrolled: prefetched B, immediate-offset LDS ----
        const float4* fb = g_fB + (kt * 27) * 64 + lane;
        float4 f0 = __ldg(fb);
        float4 f1 = __ldg(fb + 32);
        #pragma unroll
        for (int tap = 0; tap < 27; ++tap) {
            const int kd = tap / 9, kh = (tap % 9) / 3, kw = tap % 3;
            const int sh = kd * 240 + kh * 48 + kw;       // compile-time immediate
            // prefetch next tap's B while this tap's MMAs run
            float4 nf0, nf1;
            if (tap < 26) {
                nf0 = __ldg(fb + (tap + 1) * 64);
                nf1 = __ldg(fb + (tap + 1) * 64 + 32);
            }
            uint32_t bb0 = __float_as_uint(f0.x), bb1 = __float_as_uint(f0.y);
            uint32_t bb2 = __float_as_uint(f0.z), bb3 = __float_as_uint(f0.w);
            uint32_t bc0 = __float_as_uint(f1.x), bc1 = __float_as_uint(f1.y);
            uint32_t bc2 = __float_as_uint(f1.z), bc3 = __float_as_uint(f1.w);
            #pragma unroll
            for (int mt = 0; mt < 4; ++mt) {
                uint32_t a0 = __float_as_uint(aBase[mt][0][sh]);
                uint32_t a1 = __float_as_uint(aBase[mt][1][sh]);
                uint32_t a2 = __float_as_uint(aBase[mt][0][sh + 4 * PLANE]);
                uint32_t a3 = __float_as_uint(aBase[mt][1][sh + 4 * PLANE]);
                mma16n8k8(acc[mt][0], a0, a1, a2, a3, bb0, bb1);
                mma16n8k8(acc[mt][1], a0, a1, a2, a3, bb2, bb3);
                mma16n8k8(acc[mt][2], a0, a1, a2, a3, bc0, bc1);
                mma16n8k8(acc[mt][3], a0, a1, a2, a3, bc2, bc3);
            }
            f0 = nf0; f1 = nf1;
        }
    }

    // ---- epilogue: bias + masked stores ----
    const int dyw = dy0 + dsel;
    #pragma unroll
    for (int mt = 0; mt < 4; ++mt) {
        #pragma unroll
        for (int j = 0; j < 2; ++j) {
            int r = mhalf * 64 + mt * 16 + g + j * 8;
            if (r >= 126) continue;
            int hl = r / 42, wi = r - hl * 42;
            if (wi >= 40) continue;
            int sp = dyw * 1600 + (h0 + hl) * 40 + wi;
            #pragma unroll
            for (int nt = 0; nt < 4; ++nt) {
                int co = nt * 8 + 2 * c;
                out[((b * 32 + co) * 16 + t) * 64000 + sp]     = acc[mt][nt][j * 2]     + sbias[co];
                out[((b * 32 + co + 1) * 16 + t) * 64000 + sp] = acc[mt][nt][j * 2 + 1] + sbias[co + 1];
            }
        }
    }
}

extern "C" void kernel_launch(void* const* d_in, const int* in_sizes, int n_in,
                              void* d_out, int out_size) {
    const float* x = nullptr; const float* w = nullptr; const float* bias = nullptr;
    for (int i = 0; i < n_in; ++i) {
        if (in_sizes[i] == 16384000)    x    = (const float*)d_in[i];
        else if (in_sizes[i] == 20736)  w    = (const float*)d_in[i];
        else if (in_sizes[i] == 96)     bias = (const float*)d_in[i];
    }
    float* out = (float*)d_out;
    prep_fB<<<21, 256>>>(w);
    dim3 grid(14, 20, 32);
    conv4d_mma<<<grid, NT>>>(x, bias, out);
}